// round 4
// baseline (speedup 1.0000x reference)
#include <cuda_runtime.h>
#include <cuda_fp16.h>
#include <cstdint>

#define NN 100000
#define NE 1600000
#define D  128
#define NPAD (NN + 128)

typedef unsigned int u32;

// ---- scratch (static device globals; allocation-free) ----
__device__ int    g_rowptr[NN + 1];
__device__ int    g_cursor[NN];
__device__ int    g_col[NE];
// fp16 feature buffers (row-padded so GEMM tile loads never fault)
__device__ __align__(16) __half g_xh[(size_t)NPAD * D];
__device__ __align__(16) __half g_xl[(size_t)NPAD * D];
__device__ __align__(16) __half g_ah[(size_t)NPAD * D];
__device__ __align__(16) __half g_al[(size_t)NPAD * D];
__device__ __align__(16) __half g_hh[(size_t)NPAD * D];
// fp16 weights, k-pair packed: [4][64 kp][128 n] u32
__device__ __align__(16) u32 g_B[4][64 * 128];

// ---------------- helpers ----------------
__device__ __forceinline__ u32 pack2(__half a, __half b) {
    __half2 h = __halves2half2(a, b);
    return *(u32*)&h;
}
__device__ __forceinline__ void mma16816(float* c, const u32* a, const u32* b) {
    asm volatile(
        "mma.sync.aligned.m16n8k16.row.col.f32.f16.f16.f32 "
        "{%0,%1,%2,%3}, {%4,%5,%6,%7}, {%8,%9}, {%0,%1,%2,%3};"
        : "+f"(c[0]), "+f"(c[1]), "+f"(c[2]), "+f"(c[3])
        : "r"(a[0]), "r"(a[1]), "r"(a[2]), "r"(a[3]), "r"(b[0]), "r"(b[1]));
}

// ---------------- weight prep: fp32 W[k][n] -> fp16 k-pair-packed [kp][n] ----------------
__global__ void k_prepB(const float* __restrict__ W0, const float* __restrict__ W1,
                        const float* __restrict__ W2, const float* __restrict__ W3) {
    const float* Ws[4] = {W0, W1, W2, W3};
    const float* W = Ws[blockIdx.x];
    u32* b = g_B[blockIdx.x];
    for (int u = threadIdx.x; u < 64 * 128; u += blockDim.x) {
        int kp = u >> 7, n = u & 127;
        b[u] = pack2(__float2half_rn(W[(2 * kp) * D + n]),
                     __float2half_rn(W[(2 * kp + 1) * D + n]));
    }
}

// ---------------- x -> fp16 hi/lo, plus zero cursor ----------------
__global__ void k_cvt(const float* __restrict__ x, int n8, int nn) {
    int i = blockIdx.x * blockDim.x + threadIdx.x;
    if (i < nn) g_cursor[i] = 0;
    if (i >= n8) return;
    const float4* p = (const float4*)x + (size_t)i * 2;
    float4 a = p[0], b = p[1];
    float f[8] = {a.x, a.y, a.z, a.w, b.x, b.y, b.z, b.w};
    u32 hp[4], lp[4];
    #pragma unroll
    for (int q = 0; q < 4; ++q) {
        __half h0 = __float2half_rn(f[2 * q]);
        __half h1 = __float2half_rn(f[2 * q + 1]);
        __half l0 = __float2half_rn(f[2 * q] - __half2float(h0));
        __half l1 = __float2half_rn(f[2 * q + 1] - __half2float(h1));
        hp[q] = pack2(h0, h1);
        lp[q] = pack2(l0, l1);
    }
    ((uint4*)g_xh)[i] = make_uint4(hp[0], hp[1], hp[2], hp[3]);
    ((uint4*)g_xl)[i] = make_uint4(lp[0], lp[1], lp[2], lp[3]);
}

// ---------------- CSR build ----------------
__global__ void k_hist(const int* __restrict__ dst, int e) {
    int i = blockIdx.x * blockDim.x + threadIdx.x;
    if (i < e) atomicAdd(&g_cursor[dst[i]], 1);
}
// single-block scan over counts -> rowptr, cursor
__global__ void k_scan(int n, int e) {
    __shared__ int sums[1024];
    int t = threadIdx.x;
    int chunk = (n + 1023) / 1024;
    int s = t * chunk;
    int send = min(s + chunk, n);
    int sum = 0;
    for (int i = s; i < send; ++i) sum += g_cursor[i];
    sums[t] = sum;
    __syncthreads();
    for (int off = 1; off < 1024; off <<= 1) {
        int v = (t >= off) ? sums[t - off] : 0;
        __syncthreads();
        sums[t] += v;
        __syncthreads();
    }
    int run = sums[t] - sum;     // exclusive prefix
    for (int i = s; i < send; ++i) {
        int c = g_cursor[i];
        g_rowptr[i] = run;
        g_cursor[i] = run;
        run += c;
    }
    if (t == 1023) g_rowptr[n] = e;
}
__global__ void k_scatter(const int* __restrict__ src, const int* __restrict__ dst, int e) {
    int i = blockIdx.x * blockDim.x + threadIdx.x;
    if (i < e) {
        int p = atomicAdd(&g_cursor[dst[i]], 1);
        g_col[p] = src[i];
    }
}

// ---------------- mean aggregation (fp16 gather) -> fp16 hi/lo split ----------------
__global__ void k_agg16(const __half* __restrict__ feat, int n) {
    int w    = (blockIdx.x * blockDim.x + threadIdx.x) >> 5;
    int lane = threadIdx.x & 31;
    if (w >= n) return;
    int beg = g_rowptr[w], end = g_rowptr[w + 1];
    float a0 = 0.f, a1 = 0.f, a2 = 0.f, a3 = 0.f;
    int j = beg;
    for (; j + 8 <= end; j += 8) {
        uint2 u[8];
        #pragma unroll
        for (int q = 0; q < 8; ++q) {
            int s = g_col[j + q];
            u[q] = *((const uint2*)(feat + (size_t)s * D) + lane);
        }
        #pragma unroll
        for (int q = 0; q < 8; ++q) {
            float2 f0 = __half22float2(*(__half2*)&u[q].x);
            float2 f1 = __half22float2(*(__half2*)&u[q].y);
            a0 += f0.x; a1 += f0.y; a2 += f1.x; a3 += f1.y;
        }
    }
    for (; j < end; ++j) {
        int s = g_col[j];
        uint2 u = *((const uint2*)(feat + (size_t)s * D) + lane);
        float2 f0 = __half22float2(*(__half2*)&u.x);
        float2 f1 = __half22float2(*(__half2*)&u.y);
        a0 += f0.x; a1 += f0.y; a2 += f1.x; a3 += f1.y;
    }
    int deg = end - beg;
    float inv = 1.0f / (float)(deg > 1 ? deg : 1);
    float v[4] = {a0 * inv, a1 * inv, a2 * inv, a3 * inv};
    __half h[4], l[4];
    #pragma unroll
    for (int q = 0; q < 4; ++q) {
        h[q] = __float2half_rn(v[q]);
        l[q] = __float2half_rn(v[q] - __half2float(h[q]));
    }
    size_t off = (size_t)w * D + lane * 4;
    *(uint2*)(g_ah + off) = make_uint2(pack2(h[0], h[1]), pack2(h[2], h[3]));
    *(uint2*)(g_al + off) = make_uint2(pack2(l[0], l[1]), pack2(l[2], l[3]));
}

// ---------------- HMMA multi-term GEMM: out = sum_t A_t @ B[sel_t] + bias ----------------
// smem u32 layout: Asm[128][68], Bsm0[64][136], Bsm1[64][136]
#define AS 68
#define BS 136
#define SM_U32_TOTAL (128 * AS + 2 * 64 * BS)   // 26112 u32 = 104448 B

__global__ __launch_bounds__(256, 2) void k_gemm16(
    const __half* __restrict__ A0, const __half* __restrict__ A1,
    const __half* __restrict__ A2, const __half* __restrict__ A3,
    int nterms, int bsel,
    const u32* __restrict__ Bg0, const u32* __restrict__ Bg1,
    const float* __restrict__ bias,
    float* __restrict__ outf, __half* __restrict__ outh,
    int relu, int M)
{
    extern __shared__ __align__(16) u32 sm[];
    u32* Asm  = sm;
    u32* Bsm0 = sm + 128 * AS;
    u32* Bsm1 = Bsm0 + 64 * BS;

    int tid = threadIdx.x, wid = tid >> 5, lane = tid & 31;
    int g = lane >> 2, tg = lane & 3;
    int wm = (wid & 1) * 64, wn = (wid >> 1) * 32;
    int m0 = blockIdx.x * 128;

    // stage both B operands (read after the t=0 double sync)
    for (int u = tid; u < 2048; u += 256) {
        int r = u >> 5, c4 = u & 31;
        *(uint4*)&Bsm0[r * BS + c4 * 4] = ((const uint4*)Bg0)[u];
        *(uint4*)&Bsm1[r * BS + c4 * 4] = ((const uint4*)Bg1)[u];
    }

    float acc[4][4][4];
    #pragma unroll
    for (int mt = 0; mt < 4; ++mt)
        #pragma unroll
        for (int nt = 0; nt < 4; ++nt)
            #pragma unroll
            for (int c = 0; c < 4; ++c) acc[mt][nt][c] = 0.f;

    const __half* As4[4] = {A0, A1, A2, A3};

    for (int t = 0; t < nterms; ++t) {
        __syncthreads();                    // protect Asm overwrite
        const u32* Ag = (const u32*)As4[t];
        for (int u = tid; u < 2048; u += 256) {
            int r = u >> 4, c4 = u & 15;
            *(uint4*)&Asm[r * AS + c4 * 4] =
                *(const uint4*)(Ag + (size_t)(m0 + r) * 64 + c4 * 4);
        }
        __syncthreads();
        const u32* Bs = ((bsel >> t) & 1) ? Bsm1 : Bsm0;
        #pragma unroll
        for (int ks = 0; ks < 8; ++ks) {
            u32 afr[4][4];
            #pragma unroll
            for (int mt = 0; mt < 4; ++mt) {
                int r = wm + mt * 16 + g;
                afr[mt][0] = Asm[r * AS + ks * 8 + tg];
                afr[mt][1] = Asm[(r + 8) * AS + ks * 8 + tg];
                afr[mt][2] = Asm[r * AS + ks * 8 + tg + 4];
                afr[mt][3] = Asm[(r + 8) * AS + ks * 8 + tg + 4];
            }
            u32 bfr[4][2];
            #pragma unroll
            for (int nt = 0; nt < 4; ++nt) {
                int n = wn + nt * 8 + g;
                bfr[nt][0] = Bs[(ks * 8 + tg) * BS + n];
                bfr[nt][1] = Bs[(ks * 8 + tg + 4) * BS + n];
            }
            #pragma unroll
            for (int mt = 0; mt < 4; ++mt)
                #pragma unroll
                for (int nt = 0; nt < 4; ++nt)
                    mma16816(acc[mt][nt], afr[mt], bfr[nt]);
        }
    }

    // epilogue
    #pragma unroll
    for (int nt = 0; nt < 4; ++nt) {
        int ccol = wn + nt * 8 + tg * 2;
        float bv0 = __ldg(bias + ccol), bv1 = __ldg(bias + ccol + 1);
        #pragma unroll
        for (int mt = 0; mt < 4; ++mt) {
            int r0 = m0 + wm + mt * 16 + g;
            float v0 = acc[mt][nt][0] + bv0, v1 = acc[mt][nt][1] + bv1;
            float v2 = acc[mt][nt][2] + bv0, v3 = acc[mt][nt][3] + bv1;
            if (relu) {
                v0 = v0 > 0.f ? v0 : 0.f; v1 = v1 > 0.f ? v1 : 0.f;
                v2 = v2 > 0.f ? v2 : 0.f; v3 = v3 > 0.f ? v3 : 0.f;
            }
            if (outh) {
                if (r0 < M)
                    *(__half2*)(outh + (size_t)r0 * D + ccol) = __floats2half2_rn(v0, v1);
                if (r0 + 8 < M)
                    *(__half2*)(outh + (size_t)(r0 + 8) * D + ccol) = __floats2half2_rn(v2, v3);
            } else {
                if (r0 < M)
                    *(float2*)(outf + (size_t)r0 * D + ccol) = make_float2(v0, v1);
                if (r0 + 8 < M)
                    *(float2*)(outf + (size_t)(r0 + 8) * D + ccol) = make_float2(v2, v3);
            }
        }
    }
}

// ---------------- launch ----------------
extern "C" void kernel_launch(void* const* d_in, const int* in_sizes, int n_in,
                              void* d_out, int out_size)
{
    const float* x   = (const float*)d_in[0];
    const int*   ei  = (const int*)d_in[1];
    const float* W1l = (const float*)d_in[2];
    const float* b1  = (const float*)d_in[3];
    const float* W1r = (const float*)d_in[4];
    const float* W2l = (const float*)d_in[5];
    const float* b2  = (const float*)d_in[6];
    const float* W2r = (const float*)d_in[7];
    float* out = (float*)d_out;

    int N = in_sizes[0] / D;
    int E = in_sizes[1] / 2;
    const int* src = ei;
    const int* dst = ei + E;

    __half *xh, *xl, *ah, *al, *hh;
    u32 *B0, *B1, *B2, *B3;
    cudaGetSymbolAddress((void**)&xh, g_xh);
    cudaGetSymbolAddress((void**)&xl, g_xl);
    cudaGetSymbolAddress((void**)&ah, g_ah);
    cudaGetSymbolAddress((void**)&al, g_al);
    cudaGetSymbolAddress((void**)&hh, g_hh);
    {
        u32* bb;
        cudaGetSymbolAddress((void**)&bb, g_B);
        B0 = bb; B1 = bb + 8192; B2 = bb + 16384; B3 = bb + 24576;
    }

    cudaFuncSetAttribute(k_gemm16, cudaFuncAttributeMaxDynamicSharedMemorySize,
                         SM_U32_TOTAL * 4);

    int n8 = N * (D / 8);                   // uint4-granule count for cvt
    int cvtThreads = n8 > N ? n8 : N;

    k_prepB  <<<4, 256>>>(W1l, W1r, W2l, W2r);
    k_cvt    <<<(cvtThreads + 255) / 256, 256>>>(x, n8, N);
    k_hist   <<<(E + 255) / 256, 256>>>(dst, E);
    k_scan   <<<1, 1024>>>(N, E);
    k_scatter<<<(E + 255) / 256, 256>>>(src, dst, E);

    int aggBlocks  = (N * 32 + 255) / 256;
    int gemmBlocks = (N + 127) / 128;

    // layer 1: h = relu(agg(x)@W1l + x@W1r + b1)   [4 terms]
    k_agg16 <<<aggBlocks, 256>>>(xh, N);
    k_gemm16<<<gemmBlocks, 256, SM_U32_TOTAL * 4>>>(
        ah, al, xh, xl, 4, /*bsel=*/0b1100, B0, B1, b1, nullptr, hh, 1, N);

    // layer 2: out = agg(h)@W2l + h@W2r + b2       [3 terms]
    k_agg16 <<<aggBlocks, 256>>>(hh, N);
    k_gemm16<<<gemmBlocks, 256, SM_U32_TOTAL * 4>>>(
        ah, al, hh, nullptr, 3, /*bsel=*/0b100, B2, B3, b2, out, nullptr, 0, N);
}

// round 5
// speedup vs baseline: 1.4462x; 1.4462x over previous
#include <cuda_runtime.h>
#include <cuda_fp16.h>
#include <cstdint>

#define NN 100000
#define NE 1600000
#define D  128
#define NPAD (NN + 128)

typedef unsigned int u32;

// ---- scratch (static device globals; allocation-free) ----
__device__ int    g_rowptr[NN + 1];
__device__ int    g_cursor[NN];
__device__ int    g_col[NE];
__device__ int    g_bsum[128];
// fp16 feature buffers (row-padded so GEMM tile loads never fault)
__device__ __align__(16) __half g_xh[(size_t)NPAD * D];
__device__ __align__(16) __half g_xl[(size_t)NPAD * D];
__device__ __align__(16) __half g_ah[(size_t)NPAD * D];
__device__ __align__(16) __half g_al[(size_t)NPAD * D];
__device__ __align__(16) __half g_hh[(size_t)NPAD * D];
// fp16 weights, k-pair packed: [4][64 kp][128 n] u32
__device__ __align__(16) u32 g_B[4][64 * 128];

// ---------------- helpers ----------------
__device__ __forceinline__ u32 pack2(__half a, __half b) {
    __half2 h = __halves2half2(a, b);
    return *(u32*)&h;
}
__device__ __forceinline__ void mma16816(float* c, const u32* a, const u32* b) {
    asm volatile(
        "mma.sync.aligned.m16n8k16.row.col.f32.f16.f16.f32 "
        "{%0,%1,%2,%3}, {%4,%5,%6,%7}, {%8,%9}, {%0,%1,%2,%3};"
        : "+f"(c[0]), "+f"(c[1]), "+f"(c[2]), "+f"(c[3])
        : "r"(a[0]), "r"(a[1]), "r"(a[2]), "r"(a[3]), "r"(b[0]), "r"(b[1]));
}

// ---------------- weight prep: fp32 W[k][n] -> fp16 k-pair-packed [kp][n] ----------------
__global__ void k_prepB(const float* __restrict__ W0, const float* __restrict__ W1,
                        const float* __restrict__ W2, const float* __restrict__ W3) {
    const float* Ws[4] = {W0, W1, W2, W3};
    const float* W = Ws[blockIdx.x];
    u32* b = g_B[blockIdx.x];
    for (int u = threadIdx.x; u < 64 * 128; u += blockDim.x) {
        int kp = u >> 7, n = u & 127;
        b[u] = pack2(__float2half_rn(W[(2 * kp) * D + n]),
                     __float2half_rn(W[(2 * kp + 1) * D + n]));
    }
}

// ---------------- x -> fp16 hi/lo, plus zero cursor ----------------
__global__ void k_cvt(const float* __restrict__ x, int n8, int nn) {
    int i = blockIdx.x * blockDim.x + threadIdx.x;
    if (i < nn) g_cursor[i] = 0;
    if (i >= n8) return;
    const float4* p = (const float4*)x + (size_t)i * 2;
    float4 a = p[0], b = p[1];
    float f[8] = {a.x, a.y, a.z, a.w, b.x, b.y, b.z, b.w};
    u32 hp[4], lp[4];
    #pragma unroll
    for (int q = 0; q < 4; ++q) {
        __half h0 = __float2half_rn(f[2 * q]);
        __half h1 = __float2half_rn(f[2 * q + 1]);
        __half l0 = __float2half_rn(f[2 * q] - __half2float(h0));
        __half l1 = __float2half_rn(f[2 * q + 1] - __half2float(h1));
        hp[q] = pack2(h0, h1);
        lp[q] = pack2(l0, l1);
    }
    ((uint4*)g_xh)[i] = make_uint4(hp[0], hp[1], hp[2], hp[3]);
    ((uint4*)g_xl)[i] = make_uint4(lp[0], lp[1], lp[2], lp[3]);
}

// ---------------- CSR build ----------------
__global__ void k_hist(const int* __restrict__ dst, int e) {
    int i = blockIdx.x * blockDim.x + threadIdx.x;
    if (i < e) atomicAdd(&g_cursor[dst[i]], 1);
}
// hierarchical scan: per-block scan -> block offsets -> add-back
__global__ void k_scan1(int n) {
    __shared__ int sh[1024];
    int i = blockIdx.x * 1024 + threadIdx.x;
    int v = (i < n) ? g_cursor[i] : 0;
    sh[threadIdx.x] = v;
    __syncthreads();
    for (int off = 1; off < 1024; off <<= 1) {
        int t = (threadIdx.x >= (unsigned)off) ? sh[threadIdx.x - off] : 0;
        __syncthreads();
        sh[threadIdx.x] += t;
        __syncthreads();
    }
    if (i < n) g_rowptr[i] = sh[threadIdx.x] - v;   // exclusive within block
    if (threadIdx.x == 1023) g_bsum[blockIdx.x] = sh[1023];
}
__global__ void k_scan2(int nb) {
    __shared__ int sh[128];
    int v = (threadIdx.x < (unsigned)nb) ? g_bsum[threadIdx.x] : 0;
    sh[threadIdx.x] = v;
    __syncthreads();
    for (int off = 1; off < 128; off <<= 1) {
        int t = (threadIdx.x >= (unsigned)off) ? sh[threadIdx.x - off] : 0;
        __syncthreads();
        sh[threadIdx.x] += t;
        __syncthreads();
    }
    g_bsum[threadIdx.x] = sh[threadIdx.x] - v;      // exclusive block offsets
}
__global__ void k_scan3(int n, int e) {
    int i = blockIdx.x * 1024 + threadIdx.x;
    if (i < n) {
        int r = g_rowptr[i] + g_bsum[blockIdx.x];
        g_rowptr[i] = r;
        g_cursor[i] = r;
    }
    if (blockIdx.x == 0 && threadIdx.x == 0) g_rowptr[n] = e;
}
__global__ void k_scatter(const int* __restrict__ src, const int* __restrict__ dst, int e) {
    int i = blockIdx.x * blockDim.x + threadIdx.x;
    if (i < e) {
        int p = atomicAdd(&g_cursor[dst[i]], 1);
        g_col[p] = src[i];
    }
}

// ---------------- mean aggregation (fp16 gather) -> fp16 hi/lo split ----------------
__global__ void k_agg16(const __half* __restrict__ feat, int n) {
    int w    = (blockIdx.x * blockDim.x + threadIdx.x) >> 5;
    int lane = threadIdx.x & 31;
    if (w >= n) return;
    int beg = g_rowptr[w], end = g_rowptr[w + 1];
    float a0 = 0.f, a1 = 0.f, a2 = 0.f, a3 = 0.f;
    int j = beg;
    for (; j + 8 <= end; j += 8) {
        uint2 u[8];
        #pragma unroll
        for (int q = 0; q < 8; ++q) {
            int s = g_col[j + q];
            u[q] = *((const uint2*)(feat + (size_t)s * D) + lane);
        }
        #pragma unroll
        for (int q = 0; q < 8; ++q) {
            float2 f0 = __half22float2(*(__half2*)&u[q].x);
            float2 f1 = __half22float2(*(__half2*)&u[q].y);
            a0 += f0.x; a1 += f0.y; a2 += f1.x; a3 += f1.y;
        }
    }
    for (; j < end; ++j) {
        int s = g_col[j];
        uint2 u = *((const uint2*)(feat + (size_t)s * D) + lane);
        float2 f0 = __half22float2(*(__half2*)&u.x);
        float2 f1 = __half22float2(*(__half2*)&u.y);
        a0 += f0.x; a1 += f0.y; a2 += f1.x; a3 += f1.y;
    }
    int deg = end - beg;
    float inv = 1.0f / (float)(deg > 1 ? deg : 1);
    float v[4] = {a0 * inv, a1 * inv, a2 * inv, a3 * inv};
    __half h[4], l[4];
    #pragma unroll
    for (int q = 0; q < 4; ++q) {
        h[q] = __float2half_rn(v[q]);
        l[q] = __float2half_rn(v[q] - __half2float(h[q]));
    }
    size_t off = (size_t)w * D + lane * 4;
    *(uint2*)(g_ah + off) = make_uint2(pack2(h[0], h[1]), pack2(h[2], h[3]));
    *(uint2*)(g_al + off) = make_uint2(pack2(l[0], l[1]), pack2(l[2], l[3]));
}

// ---------------- HMMA multi-term GEMM: out = sum_t A_t @ B[sel_t] + bias ----------------
// smem u32 layout: Asm[128][68], Bsm0[64][136], Bsm1[64][136]
#define AS 68
#define BS 136
#define SM_U32_TOTAL (128 * AS + 2 * 64 * BS)   // 26112 u32 = 104448 B

__global__ __launch_bounds__(256, 2) void k_gemm16(
    const __half* __restrict__ A0, const __half* __restrict__ A1,
    const __half* __restrict__ A2, const __half* __restrict__ A3,
    int nterms, int bsel,
    const u32* __restrict__ Bg0, const u32* __restrict__ Bg1,
    const float* __restrict__ bias,
    float* __restrict__ outf, __half* __restrict__ outh,
    int relu, int M)
{
    extern __shared__ __align__(16) u32 sm[];
    u32* Asm  = sm;
    u32* Bsm0 = sm + 128 * AS;
    u32* Bsm1 = Bsm0 + 64 * BS;

    int tid = threadIdx.x, wid = tid >> 5, lane = tid & 31;
    int g = lane >> 2, tg = lane & 3;
    int wm = (wid & 1) * 64, wn = (wid >> 1) * 32;
    int m0 = blockIdx.x * 128;

    // stage both B operands (read after the t=0 double sync)
    for (int u = tid; u < 2048; u += 256) {
        int r = u >> 5, c4 = u & 31;
        *(uint4*)&Bsm0[r * BS + c4 * 4] = ((const uint4*)Bg0)[u];
        *(uint4*)&Bsm1[r * BS + c4 * 4] = ((const uint4*)Bg1)[u];
    }

    float acc[4][4][4];
    #pragma unroll
    for (int mt = 0; mt < 4; ++mt)
        #pragma unroll
        for (int nt = 0; nt < 4; ++nt)
            #pragma unroll
            for (int c = 0; c < 4; ++c) acc[mt][nt][c] = 0.f;

    const __half* As4[4] = {A0, A1, A2, A3};

    for (int t = 0; t < nterms; ++t) {
        __syncthreads();                    // protect Asm overwrite
        const u32* Ag = (const u32*)As4[t];
        for (int u = tid; u < 2048; u += 256) {
            int r = u >> 4, c4 = u & 15;
            *(uint4*)&Asm[r * AS + c4 * 4] =
                *(const uint4*)(Ag + (size_t)(m0 + r) * 64 + c4 * 4);
        }
        __syncthreads();
        const u32* Bs = ((bsel >> t) & 1) ? Bsm1 : Bsm0;
        #pragma unroll
        for (int ks = 0; ks < 8; ++ks) {
            u32 afr[4][4];
            #pragma unroll
            for (int mt = 0; mt < 4; ++mt) {
                int r = wm + mt * 16 + g;
                afr[mt][0] = Asm[r * AS + ks * 8 + tg];
                afr[mt][1] = Asm[(r + 8) * AS + ks * 8 + tg];
                afr[mt][2] = Asm[r * AS + ks * 8 + tg + 4];
                afr[mt][3] = Asm[(r + 8) * AS + ks * 8 + tg + 4];
            }
            u32 bfr[4][2];
            #pragma unroll
            for (int nt = 0; nt < 4; ++nt) {
                int n = wn + nt * 8 + g;
                bfr[nt][0] = Bs[(ks * 8 + tg) * BS + n];
                bfr[nt][1] = Bs[(ks * 8 + tg + 4) * BS + n];
            }
            #pragma unroll
            for (int mt = 0; mt < 4; ++mt)
                #pragma unroll
                for (int nt = 0; nt < 4; ++nt)
                    mma16816(acc[mt][nt], afr[mt], bfr[nt]);
        }
    }

    // epilogue
    #pragma unroll
    for (int nt = 0; nt < 4; ++nt) {
        int ccol = wn + nt * 8 + tg * 2;
        float bv0 = __ldg(bias + ccol), bv1 = __ldg(bias + ccol + 1);
        #pragma unroll
        for (int mt = 0; mt < 4; ++mt) {
            int r0 = m0 + wm + mt * 16 + g;
            float v0 = acc[mt][nt][0] + bv0, v1 = acc[mt][nt][1] + bv1;
            float v2 = acc[mt][nt][2] + bv0, v3 = acc[mt][nt][3] + bv1;
            if (relu) {
                v0 = v0 > 0.f ? v0 : 0.f; v1 = v1 > 0.f ? v1 : 0.f;
                v2 = v2 > 0.f ? v2 : 0.f; v3 = v3 > 0.f ? v3 : 0.f;
            }
            if (outh) {
                if (r0 < M)
                    *(__half2*)(outh + (size_t)r0 * D + ccol) = __floats2half2_rn(v0, v1);
                if (r0 + 8 < M)
                    *(__half2*)(outh + (size_t)(r0 + 8) * D + ccol) = __floats2half2_rn(v2, v3);
            } else {
                if (r0 < M)
                    *(float2*)(outf + (size_t)r0 * D + ccol) = make_float2(v0, v1);
                if (r0 + 8 < M)
                    *(float2*)(outf + (size_t)(r0 + 8) * D + ccol) = make_float2(v2, v3);
            }
        }
    }
}

// ---------------- launch ----------------
extern "C" void kernel_launch(void* const* d_in, const int* in_sizes, int n_in,
                              void* d_out, int out_size)
{
    const float* x   = (const float*)d_in[0];
    const int*   ei  = (const int*)d_in[1];
    const float* W1l = (const float*)d_in[2];
    const float* b1  = (const float*)d_in[3];
    const float* W1r = (const float*)d_in[4];
    const float* W2l = (const float*)d_in[5];
    const float* b2  = (const float*)d_in[6];
    const float* W2r = (const float*)d_in[7];
    float* out = (float*)d_out;

    int N = in_sizes[0] / D;
    int E = in_sizes[1] / 2;
    const int* src = ei;
    const int* dst = ei + E;

    __half *xh, *xl, *ah, *al, *hh;
    u32 *B0, *B1, *B2, *B3;
    cudaGetSymbolAddress((void**)&xh, g_xh);
    cudaGetSymbolAddress((void**)&xl, g_xl);
    cudaGetSymbolAddress((void**)&ah, g_ah);
    cudaGetSymbolAddress((void**)&al, g_al);
    cudaGetSymbolAddress((void**)&hh, g_hh);
    {
        u32* bb;
        cudaGetSymbolAddress((void**)&bb, g_B);
        B0 = bb; B1 = bb + 8192; B2 = bb + 16384; B3 = bb + 24576;
    }

    cudaFuncSetAttribute(k_gemm16, cudaFuncAttributeMaxDynamicSharedMemorySize,
                         SM_U32_TOTAL * 4);

    int n8 = N * (D / 8);                   // uint4-granule count for cvt
    int cvtThreads = n8 > N ? n8 : N;
    int nb = (N + 1023) / 1024;

    k_prepB  <<<4, 256>>>(W1l, W1r, W2l, W2r);
    k_cvt    <<<(cvtThreads + 255) / 256, 256>>>(x, n8, N);
    k_hist   <<<(E + 255) / 256, 256>>>(dst, E);
    k_scan1  <<<nb, 1024>>>(N);
    k_scan2  <<<1, 128>>>(nb);
    k_scan3  <<<nb, 1024>>>(N, E);
    k_scatter<<<(E + 255) / 256, 256>>>(src, dst, E);

    int aggBlocks  = (N * 32 + 255) / 256;
    int gemmBlocks = (N + 127) / 128;

    // layer 1: h = relu(agg(x)@W1l + x@W1r + b1)   [4 terms]
    k_agg16 <<<aggBlocks, 256>>>(xh, N);
    k_gemm16<<<gemmBlocks, 256, SM_U32_TOTAL * 4>>>(
        ah, al, xh, xl, 4, /*bsel=*/0b1100, B0, B1, b1, nullptr, hh, 1, N);

    // layer 2: out = agg(h)@W2l + h@W2r + b2       [3 terms]
    k_agg16 <<<aggBlocks, 256>>>(hh, N);
    k_gemm16<<<gemmBlocks, 256, SM_U32_TOTAL * 4>>>(
        ah, al, hh, nullptr, 3, /*bsel=*/0b100, B2, B3, b2, out, nullptr, 0, N);
}

// round 6
// speedup vs baseline: 1.5086x; 1.0432x over previous
#include <cuda_runtime.h>
#include <cuda_fp16.h>
#include <cstdint>

#define NN 100000
#define NE 1600000
#define D  128
#define NPAD (NN + 128)

typedef unsigned int u32;
typedef unsigned long long u64;

// ---- scratch (static device globals; allocation-free) ----
__device__ int    g_rowptr[NN + 1];
__device__ int    g_cursor[NN];
__device__ int    g_col[NE];
__device__ u64    g_bstate[128];
// feature buffers (row-padded so GEMM tile accesses never fault)
__device__ __align__(16) __half g_xh[(size_t)NPAD * D];   // x  (fp16)
__device__ __align__(16) __half g_hh[(size_t)NPAD * D];   // h  (fp16)
__device__ __align__(16) __half g_yl[(size_t)NPAD * D];   // x@W_l (fp16)
__device__ __align__(16) float  g_z [(size_t)NPAD * D];   // x@W_r + b (fp32)
// fp16 weights, k-pair packed: [4][64 kp][128 n] u32
__device__ __align__(16) u32 g_B[4][64 * 128];

// ---------------- helpers ----------------
__device__ __forceinline__ u32 pack2(__half a, __half b) {
    __half2 h = __halves2half2(a, b);
    return *(u32*)&h;
}
__device__ __forceinline__ void mma16816(float* c, const u32* a, const u32* b) {
    asm volatile(
        "mma.sync.aligned.m16n8k16.row.col.f32.f16.f16.f32 "
        "{%0,%1,%2,%3}, {%4,%5,%6,%7}, {%8,%9}, {%0,%1,%2,%3};"
        : "+f"(c[0]), "+f"(c[1]), "+f"(c[2]), "+f"(c[3])
        : "r"(a[0]), "r"(a[1]), "r"(a[2]), "r"(a[3]), "r"(b[0]), "r"(b[1]));
}

// ---------------- x -> fp16, zero cursor ----------------
__global__ void k_cvt(const float* __restrict__ x, int n8, int nn) {
    int i = blockIdx.x * blockDim.x + threadIdx.x;
    if (i < nn) g_cursor[i] = 0;
    if (i >= n8) return;
    const float4* p = (const float4*)x + (size_t)i * 2;
    float4 a = p[0], b = p[1];
    ((uint4*)g_xh)[i] = make_uint4(
        pack2(__float2half_rn(a.x), __float2half_rn(a.y)),
        pack2(__float2half_rn(a.z), __float2half_rn(a.w)),
        pack2(__float2half_rn(b.x), __float2half_rn(b.y)),
        pack2(__float2half_rn(b.z), __float2half_rn(b.w)));
}

// ---------------- CSR build ----------------
__global__ void k_hist(const int* __restrict__ dst, int e4) {
    int i = blockIdx.x * blockDim.x + threadIdx.x;
    if (i < 128) g_bstate[i] = 0ULL;
    if (i >= e4) return;
    int4 d = ((const int4*)dst)[i];
    atomicAdd(&g_cursor[d.x], 1);
    atomicAdd(&g_cursor[d.y], 1);
    atomicAdd(&g_cursor[d.z], 1);
    atomicAdd(&g_cursor[d.w], 1);
}

// single-pass decoupled-lookback scan: counts -> rowptr/cursor (exclusive)
__global__ void k_scanLB(int n, int e) {
    __shared__ int sh[1024];
    __shared__ int s_T;
    __shared__ int s_prefix;
    int bid = blockIdx.x, t = threadIdx.x;
    int i = bid * 1024 + t;
    int v = (i < n) ? g_cursor[i] : 0;
    sh[t] = v;
    __syncthreads();
    for (int off = 1; off < 1024; off <<= 1) {
        int w = (t >= off) ? sh[t - off] : 0;
        __syncthreads();
        sh[t] += w;
        __syncthreads();
    }
    if (t == 1023) s_T = sh[1023];
    if (t == 0 && bid == 0) s_prefix = 0;
    __syncthreads();
    int T = s_T;

    if (t == 0) {   // publish aggregate (bid 0 publishes final prefix directly)
        u64 st = ((u64)(unsigned)T << 32) | (bid == 0 ? 2ULL : 1ULL);
        atomicExch(&g_bstate[bid], st);
    }
    if (t < 32 && bid > 0) {       // warp-parallel lookback
        int lane = t;
        int prefix = 0;
        int base = bid - 1;
        while (true) {
            int j = base - lane;
            u64 s = (j >= 0) ? *(volatile u64*)&g_bstate[j] : 2ULL;
            unsigned f = (unsigned)(s & 3ULL);
            if (__all_sync(0xFFFFFFFFu, f != 0u)) {
                int val = (int)(unsigned)(s >> 32);
                unsigned pm = __ballot_sync(0xFFFFFFFFu, f == 2u);
                if (pm) {
                    int fp = __ffs(pm) - 1;           // closest P (smallest lane)
                    int xx = (lane <= fp) ? val : 0;
                    #pragma unroll
                    for (int o = 16; o; o >>= 1) xx += __shfl_xor_sync(0xFFFFFFFFu, xx, o);
                    prefix += xx;
                    break;
                } else {
                    int xx = val;
                    #pragma unroll
                    for (int o = 16; o; o >>= 1) xx += __shfl_xor_sync(0xFFFFFFFFu, xx, o);
                    prefix += xx;
                    base -= 32;
                }
            }
        }
        if (lane == 0) {
            atomicExch(&g_bstate[bid], ((u64)(unsigned)(prefix + T) << 32) | 2ULL);
            s_prefix = prefix;
        }
    }
    __syncthreads();
    int r = s_prefix + sh[t] - v;     // global exclusive prefix
    if (i < n) {
        g_rowptr[i] = r;
        g_cursor[i] = r;
    }
    if (bid == 0 && t == 0) g_rowptr[n] = e;
}

__global__ void k_scatter(const int* __restrict__ src, const int* __restrict__ dst, int e4) {
    int i = blockIdx.x * blockDim.x + threadIdx.x;
    if (i >= e4) return;
    int4 s = ((const int4*)src)[i];
    int4 d = ((const int4*)dst)[i];
    int p0 = atomicAdd(&g_cursor[d.x], 1); g_col[p0] = s.x;
    int p1 = atomicAdd(&g_cursor[d.y], 1); g_col[p1] = s.y;
    int p2 = atomicAdd(&g_cursor[d.z], 1); g_col[p2] = s.z;
    int p3 = atomicAdd(&g_cursor[d.w], 1); g_col[p3] = s.w;
}

// ---------------- weight prep: fp32 W[k][n] -> fp16 k-pair-packed [kp][n] ----------------
__global__ void k_prepB(const float* __restrict__ W0, const float* __restrict__ W1,
                        const float* __restrict__ W2, const float* __restrict__ W3) {
    const float* Ws[4] = {W0, W1, W2, W3};
    const float* W = Ws[blockIdx.x];
    u32* b = g_B[blockIdx.x];
    for (int u = threadIdx.x; u < 64 * 128; u += blockDim.x) {
        int kp = u >> 7, n = u & 127;
        b[u] = pack2(__float2half_rn(W[(2 * kp) * D + n]),
                     __float2half_rn(W[(2 * kp + 1) * D + n]));
    }
}

// ---------------- HMMA cat-GEMM: [yl | z] = A @ [Bl | Br] (+bias on z) ----------------
// A: fp16 [M,128]; yl: fp16 [M,128]; z: fp32 [M,128]
// smem u32: Asm[128][68], Bsm[64][264]  -> (8704 + 16896) u32 = 102400 B
#define AS 68
#define BS 264
#define SM_U32_TOTAL (128 * AS + 64 * BS)

__global__ __launch_bounds__(256, 1) void k_gemm(
    const __half* __restrict__ A,
    const u32* __restrict__ Bg0, const u32* __restrict__ Bg1,
    const float* __restrict__ bias,
    __half* __restrict__ yl, float* __restrict__ z)
{
    extern __shared__ __align__(16) u32 sm[];
    u32* Asm = sm;
    u32* Bsm = sm + 128 * AS;

    int tid = threadIdx.x, wid = tid >> 5, lane = tid & 31;
    int g = lane >> 2, tg = lane & 3;
    int wm = (wid & 1) * 64, wn = (wid >> 1) * 64;   // warp tile 64x64 of 128x256
    int m0 = blockIdx.x * 128;

    // stage B halves: W_l -> cols 0..127, W_r -> cols 128..255
    for (int u = tid; u < 2048; u += 256) {
        int r = u >> 5, c4 = u & 31;
        *(uint4*)&Bsm[r * BS + c4 * 4]       = ((const uint4*)Bg0)[u];
        *(uint4*)&Bsm[r * BS + 128 + c4 * 4] = ((const uint4*)Bg1)[u];
    }
    // stage A (fp16 rows as u32 pairs)
    const u32* Ag = (const u32*)A;
    for (int u = tid; u < 2048; u += 256) {
        int r = u >> 4, c4 = u & 15;
        *(uint4*)&Asm[r * AS + c4 * 4] =
            *(const uint4*)(Ag + (size_t)(m0 + r) * 64 + c4 * 4);
    }
    __syncthreads();

    float acc[4][8][4];
    #pragma unroll
    for (int mt = 0; mt < 4; ++mt)
        #pragma unroll
        for (int nt = 0; nt < 8; ++nt)
            #pragma unroll
            for (int c = 0; c < 4; ++c) acc[mt][nt][c] = 0.f;

    #pragma unroll
    for (int ks = 0; ks < 8; ++ks) {
        u32 afr[4][4];
        #pragma unroll
        for (int mt = 0; mt < 4; ++mt) {
            int r = wm + mt * 16 + g;
            afr[mt][0] = Asm[r * AS + ks * 8 + tg];
            afr[mt][1] = Asm[(r + 8) * AS + ks * 8 + tg];
            afr[mt][2] = Asm[r * AS + ks * 8 + tg + 4];
            afr[mt][3] = Asm[(r + 8) * AS + ks * 8 + tg + 4];
        }
        u32 bfr[8][2];
        #pragma unroll
        for (int nt = 0; nt < 8; ++nt) {
            int n = wn + nt * 8 + g;
            bfr[nt][0] = Bsm[(ks * 8 + tg) * BS + n];
            bfr[nt][1] = Bsm[(ks * 8 + tg + 4) * BS + n];
        }
        #pragma unroll
        for (int mt = 0; mt < 4; ++mt)
            #pragma unroll
            for (int nt = 0; nt < 8; ++nt)
                mma16816(acc[mt][nt], afr[mt], bfr[nt]);
    }

    // epilogue: cols <128 -> yl (fp16); cols >=128 -> z (fp32, +bias)
    #pragma unroll
    for (int nt = 0; nt < 8; ++nt) {
        int ccol = wn + nt * 8 + tg * 2;
        if (ccol < 128) {
            #pragma unroll
            for (int mt = 0; mt < 4; ++mt) {
                int r0 = m0 + wm + mt * 16 + g;
                *(__half2*)(yl + (size_t)r0 * D + ccol) =
                    __floats2half2_rn(acc[mt][nt][0], acc[mt][nt][1]);
                *(__half2*)(yl + (size_t)(r0 + 8) * D + ccol) =
                    __floats2half2_rn(acc[mt][nt][2], acc[mt][nt][3]);
            }
        } else {
            int zc = ccol - 128;
            float bv0 = __ldg(bias + zc), bv1 = __ldg(bias + zc + 1);
            #pragma unroll
            for (int mt = 0; mt < 4; ++mt) {
                int r0 = m0 + wm + mt * 16 + g;
                *(float2*)(z + (size_t)r0 * D + zc) =
                    make_float2(acc[mt][nt][0] + bv0, acc[mt][nt][1] + bv1);
                *(float2*)(z + (size_t)(r0 + 8) * D + zc) =
                    make_float2(acc[mt][nt][2] + bv0, acc[mt][nt][3] + bv1);
            }
        }
    }
}

// ---------------- fused mean-agg + add-self + (relu) ----------------
// out = [relu](mean_{src in N(w)} yl[src]) + z[w]); writes fp16 (outh) or fp32 (outf)
__global__ void k_aggf(const __half* __restrict__ yl, const float* __restrict__ z,
                       __half* __restrict__ outh, float* __restrict__ outf,
                       int relu, int n)
{
    int w    = (blockIdx.x * blockDim.x + threadIdx.x) >> 5;
    int lane = threadIdx.x & 31;
    if (w >= n) return;
    int beg = g_rowptr[w], end = g_rowptr[w + 1];
    float a0 = 0.f, a1 = 0.f, a2 = 0.f, a3 = 0.f;
    int j = beg;
    for (; j + 8 <= end; j += 8) {
        uint2 u[8];
        #pragma unroll
        for (int q = 0; q < 8; ++q) {
            int s = g_col[j + q];
            u[q] = *((const uint2*)(yl + (size_t)s * D) + lane);
        }
        #pragma unroll
        for (int q = 0; q < 8; ++q) {
            float2 f0 = __half22float2(*(__half2*)&u[q].x);
            float2 f1 = __half22float2(*(__half2*)&u[q].y);
            a0 += f0.x; a1 += f0.y; a2 += f1.x; a3 += f1.y;
        }
    }
    for (; j < end; ++j) {
        int s = g_col[j];
        uint2 u = *((const uint2*)(yl + (size_t)s * D) + lane);
        float2 f0 = __half22float2(*(__half2*)&u.x);
        float2 f1 = __half22float2(*(__half2*)&u.y);
        a0 += f0.x; a1 += f0.y; a2 += f1.x; a3 += f1.y;
    }
    int deg = end - beg;
    float inv = 1.0f / (float)(deg > 1 ? deg : 1);
    float4 zr = *((const float4*)(z + (size_t)w * D) + lane);
    float v0 = a0 * inv + zr.x, v1 = a1 * inv + zr.y;
    float v2 = a2 * inv + zr.z, v3 = a3 * inv + zr.w;
    if (relu) {
        v0 = v0 > 0.f ? v0 : 0.f; v1 = v1 > 0.f ? v1 : 0.f;
        v2 = v2 > 0.f ? v2 : 0.f; v3 = v3 > 0.f ? v3 : 0.f;
    }
    if (outh) {
        *((uint2*)(outh + (size_t)w * D) + lane) =
            make_uint2(pack2(__float2half_rn(v0), __float2half_rn(v1)),
                       pack2(__float2half_rn(v2), __float2half_rn(v3)));
    } else {
        *((float4*)(outf + (size_t)w * D) + lane) = make_float4(v0, v1, v2, v3);
    }
}

// ---------------- launch ----------------
extern "C" void kernel_launch(void* const* d_in, const int* in_sizes, int n_in,
                              void* d_out, int out_size)
{
    const float* x   = (const float*)d_in[0];
    const int*   ei  = (const int*)d_in[1];
    const float* W1l = (const float*)d_in[2];
    const float* b1  = (const float*)d_in[3];
    const float* W1r = (const float*)d_in[4];
    const float* W2l = (const float*)d_in[5];
    const float* b2  = (const float*)d_in[6];
    const float* W2r = (const float*)d_in[7];
    float* out = (float*)d_out;

    int N = in_sizes[0] / D;
    int E = in_sizes[1] / 2;
    const int* src = ei;
    const int* dst = ei + E;

    __half *xh, *hh, *yl;
    float* z;
    u32 *B0, *B1, *B2, *B3;
    cudaGetSymbolAddress((void**)&xh, g_xh);
    cudaGetSymbolAddress((void**)&hh, g_hh);
    cudaGetSymbolAddress((void**)&yl, g_yl);
    cudaGetSymbolAddress((void**)&z,  g_z);
    {
        u32* bb;
        cudaGetSymbolAddress((void**)&bb, g_B);
        B0 = bb; B1 = bb + 8192; B2 = bb + 16384; B3 = bb + 24576;
    }

    cudaFuncSetAttribute(k_gemm, cudaFuncAttributeMaxDynamicSharedMemorySize,
                         SM_U32_TOTAL * 4);

    int n8 = N * (D / 8);
    int e4 = (E + 3) / 4;
    int nb = (N + 1023) / 1024;

    k_cvt    <<<(n8 + 255) / 256, 256>>>(x, n8, N);
    k_hist   <<<(e4 + 255) / 256, 256>>>(dst, e4);
    k_scanLB <<<nb, 1024>>>(N, E);
    k_scatter<<<(e4 + 255) / 256, 256>>>(src, dst, e4);
    k_prepB  <<<4, 256>>>(W1l, W1r, W2l, W2r);

    int aggBlocks  = (N * 32 + 255) / 256;
    int gemmBlocks = (N + 127) / 128;

    // layer 1: yl = x@W1l, z = x@W1r + b1;  h = relu(mean(yl) + z)
    k_gemm<<<gemmBlocks, 256, SM_U32_TOTAL * 4>>>(xh, B0, B1, b1, yl, z);
    k_aggf<<<aggBlocks, 256>>>(yl, z, hh, nullptr, 1, N);

    // layer 2: yl = h@W2l, z = h@W2r + b2;  out = mean(yl) + z
    k_gemm<<<gemmBlocks, 256, SM_U32_TOTAL * 4>>>(hh, B2, B3, b2, yl, z);
    k_aggf<<<aggBlocks, 256>>>(yl, z, nullptr, out, 0, N);
}